// round 13
// baseline (speedup 1.0000x reference)
#include <cuda_runtime.h>
#include <cuda_fp16.h>
#include <cstdint>

// Winograd F(2x2,3x3) for: out[i,j,f] = bias[f] + sum_{a,b,c} xp[i+a, j+b, c] * g[f,c,a,b]
// where xp = x zero-padded by 3 at top/left (xp[r] = x[r-3]) and g = 180-flipped kernel.
// (Equivalent to the validated direct form out[i,j] = sum x[i-1-th, j-1-tw] k[th,tw].)
// Per position (u,v) of the 4x4 transform: M[tile,f] = sum_c V[tile,c] * U[f,c]  (fp16 mma.sync,
// fp32 accum); O = AT M A accumulated with compile-time {0,+1,-1} coefficients.

#define BATCH 8
#define HH 64
#define WW 64
#define CIN 64
#define FF 64

// smem map (bytes)
#define XP_OFF   0                       // 6 rows x 68 cols x 128B  = 52224
#define V_OFF    52224                   // 16 pos x 64 tiles x 128B = 131072
#define U_OFF    183296                  // 4 bufs x 64 f x 128B     = 32768
#define BIAS_OFF 216064                  // 64 floats
#define SMEM_BYTES 216320

__device__ __forceinline__ uint32_t smem_u32(const void* p) {
    uint32_t a;
    asm("{ .reg .u64 t; cvta.to.shared.u64 t, %1; cvt.u32.u64 %0, t; }" : "=r"(a) : "l"(p));
    return a;
}
__device__ __forceinline__ void ldsm4(uint32_t* r, uint32_t addr) {
    asm volatile("ldmatrix.sync.aligned.m8n8.x4.shared.b16 {%0,%1,%2,%3}, [%4];"
                 : "=r"(r[0]), "=r"(r[1]), "=r"(r[2]), "=r"(r[3]) : "r"(addr));
}
__device__ __forceinline__ void mma16(float* d, const uint32_t* a, uint32_t b0, uint32_t b1) {
    asm volatile("mma.sync.aligned.m16n8k16.row.col.f32.f16.f16.f32 "
                 "{%0,%1,%2,%3}, {%4,%5,%6,%7}, {%8,%9}, {%0,%1,%2,%3};"
                 : "+f"(d[0]), "+f"(d[1]), "+f"(d[2]), "+f"(d[3])
                 : "r"(a[0]), "r"(a[1]), "r"(a[2]), "r"(a[3]), "r"(b0), "r"(b1));
}
__device__ __forceinline__ void cp16(uint32_t dst, const void* src) {
    asm volatile("cp.async.cg.shared.global [%0], [%1], 16;"
                 :: "r"(dst), "l"(__cvta_generic_to_global(src)) : "memory");
}
#define CP_COMMIT() asm volatile("cp.async.commit_group;" ::: "memory")
#define CP_WAIT1()  asm volatile("cp.async.wait_group 1;" ::: "memory")
#define CP_WAIT0()  asm volatile("cp.async.wait_group 0;" ::: "memory")

// Transformed weights U[pos][f][c] fp16, pos = u*4+v  (8KB per position)
__device__ __half g_wu[16 * FF * CIN];

__global__ void wtrans_kernel(const float* __restrict__ kin) {
    int idx = blockIdx.x * blockDim.x + threadIdx.x;
    if (idx >= FF * CIN) return;
    int c = idx & 63, f = idx >> 6;
    // g = flipped kernel
    float g[3][3];
    #pragma unroll
    for (int a = 0; a < 3; ++a)
        #pragma unroll
        for (int bb = 0; bb < 3; ++bb)
            g[a][bb] = kin[((f * CIN + c) * 3 + (2 - a)) * 3 + (2 - bb)];
    // T = G g   (G = [1,0,0; .5,.5,.5; .5,-.5,.5; 0,0,1])
    float T[4][3];
    #pragma unroll
    for (int j = 0; j < 3; ++j) {
        T[0][j] = g[0][j];
        T[1][j] = 0.5f * (g[0][j] + g[1][j] + g[2][j]);
        T[2][j] = 0.5f * (g[0][j] - g[1][j] + g[2][j]);
        T[3][j] = g[2][j];
    }
    // U = T G^T
    #pragma unroll
    for (int u = 0; u < 4; ++u) {
        float U0 = T[u][0];
        float U1 = 0.5f * (T[u][0] + T[u][1] + T[u][2]);
        float U2 = 0.5f * (T[u][0] - T[u][1] + T[u][2]);
        float U3 = T[u][2];
        g_wu[(u * 4 + 0) * (FF * CIN) + f * CIN + c] = __float2half_rn(U0);
        g_wu[(u * 4 + 1) * (FF * CIN) + f * CIN + c] = __float2half_rn(U1);
        g_wu[(u * 4 + 2) * (FF * CIN) + f * CIN + c] = __float2half_rn(U2);
        g_wu[(u * 4 + 3) * (FF * CIN) + f * CIN + c] = __float2half_rn(U3);
    }
}

__device__ __forceinline__ float2 f2add(float2 a, float2 b) { return make_float2(a.x + b.x, a.y + b.y); }
__device__ __forceinline__ float2 f2sub(float2 a, float2 b) { return make_float2(a.x - b.x, a.y - b.y); }

__global__ __launch_bounds__(256, 1)
void conv_wino(const float* __restrict__ x,
               const float* __restrict__ bias,
               float* __restrict__ out) {
    extern __shared__ char smc[];
    const uint32_t sb  = smem_u32(smc);
    const uint32_t sbV = sb + V_OFF;
    const uint32_t sbU = sb + U_OFF;
    float* sbias = (float*)(smc + BIAS_OFF);

    const int tid = threadIdx.x;
    const int b  = blockIdx.x >> 4;
    const int r0 = blockIdx.x & 15;            // CTA covers out rows 4*r0..4*r0+3, all 64 cols

    // U prefetch: 512 x 16B chunks per position, XOR-swizzled rows [f][c]
    auto issueU = [&](int p) {
        uint32_t dbase = sbU + (uint32_t)((p & 3) * 8192);
        const __half* s0 = g_wu + p * (FF * CIN);
        #pragma unroll
        for (int k = 0; k < 2; ++k) {
            int ch = tid + 256 * k;            // 0..511
            int f  = ch >> 3, k8 = ch & 7;
            cp16(dbase + (uint32_t)(f * 128 + ((k8 ^ (f & 7)) << 4)), s0 + f * CIN + k8 * 8);
        }
        CP_COMMIT();
    };
    issueU(0); issueU(1);

    // zero xp (covers top/left padding)
    {
        uint4 z = make_uint4(0u, 0u, 0u, 0u);
        #pragma unroll
        for (int k = 0; k < 13; ++k) {
            int idx = tid + 256 * k;
            if (idx < 52224 / 16) ((uint4*)smc)[idx] = z;
        }
        if (tid < 64) sbias[tid] = bias[tid];
    }
    __syncthreads();

    // stage xp rows 0..5 (= x rows 4*r0-3 .. 4*r0+2), cols 3..65 (= x cols 0..62), fp16
    {
        #pragma unroll
        for (int k = 0; k < 24; ++k) {
            int it = tid + 256 * k;            // 6 rows x 63 cols x 16 c4 = 6048
            if (it >= 6048) break;
            int c4   = it & 15;
            int colx = (it >> 4) % 63;
            int r    = (it >> 4) / 63;
            int gr   = 4 * r0 - 3 + r;
            if (gr < 0) continue;
            float4 v = ((const float4*)x)[((size_t)(b * HH + gr) * WW + colx) * 16 + c4];
            __half2 h0 = __float22half2_rn(make_float2(v.x, v.y));
            __half2 h1 = __float22half2_rn(make_float2(v.z, v.w));
            uint2 w;
            w.x = *(uint32_t*)&h0;
            w.y = *(uint32_t*)&h1;
            *(uint2*)(smc + (r * 68 + colx + 3) * 128 + c4 * 8) = w;
        }
    }
    __syncthreads();

    // input transform: V[u,v][tile][c] for all 16 positions (fp32 adds, one fp16 rounding)
    {
        #pragma unroll
        for (int k = 0; k < 8; ++k) {
            int it = tid + 256 * k;            // 64 tiles x 32 c2 = 2048
            int t = it >> 5, c2 = it & 31;
            int tr = t >> 5, tc = t & 31;
            const char* xb = smc + ((2 * tr) * 68 + 2 * tc) * 128 + c2 * 4;
            float2 d[4][4];
            #pragma unroll
            for (int rr = 0; rr < 4; ++rr)
                #pragma unroll
                for (int cc = 0; cc < 4; ++cc)
                    d[rr][cc] = __half22float2(*(const __half2*)(xb + (rr * 68 + cc) * 128));
            float2 F[4][4];
            #pragma unroll
            for (int cc = 0; cc < 4; ++cc) {
                F[0][cc] = f2sub(d[0][cc], d[2][cc]);
                F[1][cc] = f2add(d[1][cc], d[2][cc]);
                F[2][cc] = f2sub(d[2][cc], d[1][cc]);
                F[3][cc] = f2sub(d[1][cc], d[3][cc]);
            }
            uint32_t vdst = sbV + (uint32_t)(t * 128 + (((c2 >> 2) ^ (t & 7)) << 4) + (c2 & 3) * 4);
            #pragma unroll
            for (int u = 0; u < 4; ++u) {
                float2 V0 = f2sub(F[u][0], F[u][2]);
                float2 V1 = f2add(F[u][1], F[u][2]);
                float2 V2 = f2sub(F[u][2], F[u][1]);
                float2 V3 = f2sub(F[u][1], F[u][3]);
                *(__half2*)(smc + (vdst - sb) + (u * 4 + 0) * 8192) = __float22half2_rn(V0);
                *(__half2*)(smc + (vdst - sb) + (u * 4 + 1) * 8192) = __float22half2_rn(V1);
                *(__half2*)(smc + (vdst - sb) + (u * 4 + 2) * 8192) = __float22half2_rn(V2);
                *(__half2*)(smc + (vdst - sb) + (u * 4 + 3) * 8192) = __float22half2_rn(V3);
            }
        }
    }

    // warp tiling: 8 warps = 4 m-groups (16 tiles) x 2 n-groups (32 f)
    const int lane = tid & 31, wid = tid >> 5;
    const int lq = lane >> 2, lr = lane & 3;
    const int wm = wid & 3;
    const int wn = wid >> 2;
    const int mA = lane & 15;
    const int kc = lane >> 4;
    const int fB = (lane & 7) + 8 * ((lane >> 3) & 1);
    const int sA = mA & 7;                     // A row = 16*wm + mA
    const int sB = fB & 7;                     // B rows = 32*wn + fB (+16)
    const uint32_t aAbase = sbV + (uint32_t)((16 * wm + mA) * 128);
    const uint32_t aBoff  = (uint32_t)((32 * wn + fB) * 128);

    constexpr int AT0[4] = {1, 1, 1, 0};
    constexpr int AT1[4] = {0, 1, -1, -1};

    float O[4][2][2][2][2];                    // [nt][tq][fv][py][px]
    #pragma unroll
    for (int a1 = 0; a1 < 4; ++a1)
        #pragma unroll
        for (int a2 = 0; a2 < 2; ++a2)
            #pragma unroll
            for (int a3 = 0; a3 < 2; ++a3)
                #pragma unroll
                for (int a4 = 0; a4 < 2; ++a4) {
                    O[a1][a2][a3][a4][0] = 0.0f;
                    O[a1][a2][a3][a4][1] = 0.0f;
                }

    #pragma unroll
    for (int p = 0; p < 16; ++p) {
        if (p < 15) { CP_WAIT1(); } else { CP_WAIT0(); }
        __syncthreads();                       // U[p] landed; V ready (p=0); buf (p+2)&3 free
        if (p < 14) issueU(p + 2);

        float mac[16];
        #pragma unroll
        for (int q = 0; q < 16; ++q) mac[q] = 0.0f;

        const uint32_t va = aAbase + (uint32_t)(p * 8192);
        const uint32_t ub = sbU + (uint32_t)((p & 3) * 8192);
        #pragma unroll
        for (int ks = 0; ks < 4; ++ks) {
            const int cc = 2 * ks + kc;
            uint32_t a[4], b0[4], b1[4];
            ldsm4(a,  va + ((cc ^ sA) << 4));
            ldsm4(b0, ub + aBoff + ((cc ^ sB) << 4));
            ldsm4(b1, ub + aBoff + 16 * 128 + ((cc ^ sB) << 4));
            mma16(mac + 0,  a, b0[0], b0[2]);
            mma16(mac + 4,  a, b0[1], b0[3]);
            mma16(mac + 8,  a, b1[0], b1[2]);
            mma16(mac + 12, a, b1[1], b1[3]);
        }

        // O += AT[py][u] * AT[px][v] * M   (compile-time 0/+1/-1)
        const int u = p >> 2, v = p & 3;
        #pragma unroll
        for (int nt = 0; nt < 4; ++nt)
            #pragma unroll
            for (int j = 0; j < 4; ++j) {
                float m = mac[nt * 4 + j];
                const int tq = j >> 1, fv = j & 1;
                #pragma unroll
                for (int py = 0; py < 2; ++py) {
                    const int cy = py ? AT1[u] : AT0[u];
                    if (cy == 0) continue;
                    #pragma unroll
                    for (int px = 0; px < 2; ++px) {
                        const int cx = px ? AT1[v] : AT0[v];
                        const int c2 = cy * cx;
                        if (c2 == 0) continue;
                        if (c2 > 0) O[nt][tq][fv][py][px] += m;
                        else        O[nt][tq][fv][py][px] -= m;
                    }
                }
            }
    }

    // epilogue: bias + store (tile t = 16*wm + lq + 8*tq -> out rows 4*r0+2*tr+py, col 2*tc+px)
    #pragma unroll
    for (int nt = 0; nt < 4; ++nt) {
        const int f = 32 * wn + nt * 8 + 2 * lr;
        const float b0f = sbias[f], b1f = sbias[f + 1];
        #pragma unroll
        for (int tq = 0; tq < 2; ++tq) {
            const int t = 16 * wm + lq + 8 * tq;
            const int tr = t >> 5, tc = t & 31;
            #pragma unroll
            for (int py = 0; py < 2; ++py) {
                const int i = 4 * r0 + 2 * tr + py;
                #pragma unroll
                for (int px = 0; px < 2; ++px) {
                    const int j = 2 * tc + px;
                    float2 val = make_float2(O[nt][tq][0][py][px] + b0f,
                                             O[nt][tq][1][py][px] + b1f);
                    *(float2*)(out + (((size_t)(b * HH + i) * WW + j) * FF) + f) = val;
                }
            }
        }
    }
}

extern "C" void kernel_launch(void* const* d_in, const int* in_sizes, int n_in,
                              void* d_out, int out_size) {
    const float* x    = (const float*)d_in[0];
    const float* kern = (const float*)d_in[1];
    const float* bias = (const float*)d_in[2];
    float* out = (float*)d_out;

    cudaFuncSetAttribute(conv_wino, cudaFuncAttributeMaxDynamicSharedMemorySize, SMEM_BYTES);

    wtrans_kernel<<<16, 256>>>(kern);
    conv_wino<<<BATCH * 16, 256, SMEM_BYTES>>>(x, bias, out);
}